// round 14
// baseline (speedup 1.0000x reference)
#include <cuda_runtime.h>
#include <cuda_fp16.h>
#include <math.h>
#include <stdint.h>

// Problem shape (fixed by the reference)
#define BB 4
#define TT 2048
#define EE 768
#define HH 8
#define HE 6144          // H*E
#define MR 8192          // B*T
#define NSPLIT 3         // split-K for final projection

// Scratch (allocation-free rule -> __device__ globals)
__device__ __half g_x16[(size_t)MR * EE];                 // x in fp16
__device__ __half g_w16[(size_t)4 * HE * EE];             // Wq|Wk|Wv|Wu fp16 (native layout)
__device__ __half g_qkv[(size_t)3 * MR * HE];             // q|k|v fp16
__device__ __half g_p16[(size_t)BB * HH * (size_t)TT * TT]; // unnormalized exp(logit)
__device__ float  g_rowsum[(size_t)BB * HH * TT];         // per-row sum of exp
__device__ __half g_ho[(size_t)MR * HE];                  // attention out fp16
__device__ float  g_psum[(size_t)NSPLIT * MR * EE];       // split-K partials

// Tiling: CTA 256x128, BK=64 halfs, 8 warps (4Mx2N, 64x64 warp tile),
// 3-stage cp.async ring, XOR swizzle. 1 CTA/SM (144KB smem).
#define BKH 64
#define STAGE_A 32768                   // A tile: 256 rows x 128 B
#define STAGE_B 16384                   // B tile: 16 KB (both layouts)
#define NSTAGE 3
#define SMEM_TOTAL (NSTAGE * (STAGE_A + STAGE_B))   // 147456 B

__device__ __forceinline__ void cp_async16(uint32_t smem_dst, const void* gmem_src) {
    asm volatile("cp.async.cg.shared.global [%0], [%1], 16;" :: "r"(smem_dst), "l"(gmem_src));
}
__device__ __forceinline__ void cp_commit() { asm volatile("cp.async.commit_group;" ::: "memory"); }
template<int N>
__device__ __forceinline__ void cp_wait() { asm volatile("cp.async.wait_group %0;" :: "n"(N) : "memory"); }
__device__ __forceinline__ void ldsm_x4(uint32_t (&d)[4], uint32_t addr) {
    asm volatile("ldmatrix.sync.aligned.m8n8.x4.shared.b16 {%0,%1,%2,%3}, [%4];"
        : "=r"(d[0]), "=r"(d[1]), "=r"(d[2]), "=r"(d[3]) : "r"(addr));
}
__device__ __forceinline__ void ldsm_x4_t(uint32_t (&d)[4], uint32_t addr) {
    asm volatile("ldmatrix.sync.aligned.m8n8.x4.trans.shared.b16 {%0,%1,%2,%3}, [%4];"
        : "=r"(d[0]), "=r"(d[1]), "=r"(d[2]), "=r"(d[3]) : "r"(addr));
}

// ---------------------------------------------------------------------------
// fp16 tensor-core GEMM (m16n8k16). C = alpha * A[M,K] @ B (+epilogue).
// TRANSB=false: B is K-major [N,K] rows (scores: B=k).
// TRANSB=true:  B is N-major [K,N] rows (W, v) -> ldmatrix.trans.
// MODE: 0 = fp16 out (alpha), 1 = fp32 out (alpha), 2 = EXPSUM, 3 = NORM.
// CTA tile 256x128, 8 warps (4 along M x 2 along N), warp tile 64x64.
// ---------------------------------------------------------------------------
template<int MODE, bool TRANSB>
__global__ __launch_bounds__(256, 1)
void hgemm(const __half* __restrict__ A, const __half* __restrict__ B,
           void* __restrict__ Cv, float* __restrict__ rowsum,
           int K, int lda, int ldb, int ldc,
           int nh, long sAb, long sAh, long sBb, long sBh,
           long sCb, long sCh, float alpha)
{
    extern __shared__ __half smem[];
    const uint32_t smem_u = (uint32_t)__cvta_generic_to_shared(smem);
    const uint32_t smem_b0 = smem_u + NSTAGE * STAGE_A;

    const int bz = blockIdx.z;
    const int bb = bz / nh;
    const int hh = bz - bb * nh;
    A += (long)bb * sAb + (long)hh * sAh;
    B += (long)bb * sBb + (long)hh * sBh;
    float*  Cf = (float*)Cv  + bb * sCb + hh * sCh;
    __half* Ch = (__half*)Cv + bb * sCb + hh * sCh;
    if (MODE == 2 || MODE == 3) rowsum += (long)bz * TT;

    const int tid  = threadIdx.x;
    const int warp = tid >> 5, lane = tid & 31;
    const int g    = lane >> 2, tig = lane & 3;
    const int r8   = lane & 7, j = lane >> 3;      // LDSM lane roles
    const int wm   = (warp >> 1) * 64;   // 4 warps along M (0..192)
    const int wn   = (warp & 1)  * 64;   // 2 warps along N
    const int row0 = blockIdx.y * 256;
    const int col0 = blockIdx.x * 128;

    // A fragments (K-major, 128B rows): rowbase + ((csel + kf*32) ^ xm)
    uint32_t arow[4], axm[4];
    const uint32_t acsel = (uint32_t)(j >> 1) << 4;
    #pragma unroll
    for (int mi = 0; mi < 4; mi++) {
        int r = wm + mi * 16 + (j & 1) * 8 + r8;
        arow[mi] = (uint32_t)r << 7;
        axm[mi]  = (uint32_t)(r & 7) << 4;
    }
    // B fragments
    uint32_t brow[4], bxm[4];            // non-trans (K-major 128B rows)
    uint32_t btb[4];                     // trans (N-major 256B rows)
    const uint32_t bcsel = (uint32_t)(j & 1) << 4;
    if (!TRANSB) {
        #pragma unroll
        for (int p = 0; p < 4; p++) {
            int r = wn + p * 16 + (j >> 1) * 8 + r8;
            brow[p] = (uint32_t)r << 7;
            bxm[p]  = (uint32_t)(r & 7) << 4;
        }
    } else {
        // block j: row = (j&1)*8 + r8 (k-oct), col = wn*2 + p*32 + (j>>1)*16
        // swizzle XOR applied to the FULL 16B-aligned column offset (< 256)
        const uint32_t xtm = (uint32_t)r8 << 4;
        #pragma unroll
        for (int p = 0; p < 4; p++)
            btb[p] = (uint32_t)((j & 1) * 8 + r8) * 256
                   + (((uint32_t)(wn * 2 + p * 32 + (j >> 1) * 16)) ^ xtm);
    }

    float acc[4][8][4] = {};  // [mi][ni][reg]

    // Loaders (256 threads).
    // A: 256 rows x 128B -> 2048 chunks -> 8 passes, rr = (tid>>3) + p*32.
    // B non-trans: 128 rows x 128B -> 4 passes, rr = (tid>>3) + p*32.
    // B trans: 64 rows x 256B -> 4 passes, rr = (tid>>4) + p*16.
    const int a_rr = tid >> 3;
    const uint32_t a_cb = (uint32_t)(tid & 7) << 4;
    const int t_rr = tid >> 4;
    const uint32_t t_c16 = (uint32_t)(tid & 15) << 4;

    #define LOAD_TILE(KT, ST)                                                         \
    {                                                                                 \
        const int _k0 = (KT) * BKH;                                                   \
        const uint32_t _sa = smem_u + (ST) * STAGE_A;                                 \
        const uint32_t _sb = smem_b0 + (ST) * STAGE_B;                                \
        _Pragma("unroll")                                                             \
        for (int p = 0; p < 8; p++) {                                                 \
            int rr = a_rr + p * 32;                                                   \
            uint32_t off = ((uint32_t)rr << 7) + (a_cb ^ ((uint32_t)(rr & 7) << 4));  \
            cp_async16(_sa + off, &A[(size_t)(row0 + rr) * lda + _k0 + (a_cb >> 1)]); \
        }                                                                             \
        if (TRANSB) {                                                                 \
            _Pragma("unroll")                                                         \
            for (int p = 0; p < 4; p++) {                                             \
                int rr = t_rr + p * 16;                                               \
                uint32_t off = ((uint32_t)rr << 8) + (t_c16 ^ ((uint32_t)(rr & 7) << 4)); \
                cp_async16(_sb + off, &B[(size_t)(_k0 + rr) * ldb + col0 + (t_c16 >> 1)]); \
            }                                                                         \
        } else {                                                                      \
            _Pragma("unroll")                                                         \
            for (int p = 0; p < 4; p++) {                                             \
                int rr = a_rr + p * 32;                                               \
                uint32_t off = ((uint32_t)rr << 7) + (a_cb ^ ((uint32_t)(rr & 7) << 4)); \
                cp_async16(_sb + off, &B[(size_t)(col0 + rr) * ldb + _k0 + (a_cb >> 1)]); \
            }                                                                         \
        }                                                                             \
        cp_commit();                                                                  \
    }

    const int nt = K / BKH;
    LOAD_TILE(0, 0);
    if (nt > 1) LOAD_TILE(1, 1);

    int st = 0;
    for (int kt = 0; kt < nt; kt++) {
        if (kt + 1 < nt) cp_wait<1>(); else cp_wait<0>();
        __syncthreads();

        if (kt + 2 < nt) {
            int st2 = st + 2; if (st2 >= NSTAGE) st2 -= NSTAGE;
            LOAD_TILE(kt + 2, st2);
        }

        const uint32_t as_u = smem_u + st * STAGE_A;
        const uint32_t bs_u = smem_b0 + st * STAGE_B;

        #pragma unroll
        for (int kf = 0; kf < 4; kf++) {          // 4 x k16 steps
            uint32_t af[4][4];
            uint32_t bf[4][4];
            #pragma unroll
            for (int p = 0; p < 4; p++) {
                ldsm_x4(af[p], as_u + arow[p] + ((acsel + (kf << 5)) ^ axm[p]));
                if (TRANSB) {
                    // kf advances 16 k-rows = 16*256 B; (row&7) unchanged
                    ldsm_x4_t(bf[p], bs_u + btb[p] + ((uint32_t)kf << 12));
                } else {
                    ldsm_x4(bf[p], bs_u + brow[p] + ((bcsel + (kf << 5)) ^ bxm[p]));
                }
            }

            #pragma unroll
            for (int mi = 0; mi < 4; mi++)
                #pragma unroll
                for (int ni = 0; ni < 8; ni++) {
                    const uint32_t b0 = bf[ni >> 1][(ni & 1) * 2 + 0];
                    const uint32_t b1 = bf[ni >> 1][(ni & 1) * 2 + 1];
                    asm volatile(
                        "mma.sync.aligned.m16n8k16.row.col.f32.f16.f16.f32 "
                        "{%0,%1,%2,%3},{%4,%5,%6,%7},{%8,%9},{%0,%1,%2,%3};"
                        : "+f"(acc[mi][ni][0]), "+f"(acc[mi][ni][1]),
                          "+f"(acc[mi][ni][2]), "+f"(acc[mi][ni][3])
                        : "r"(af[mi][0]), "r"(af[mi][1]), "r"(af[mi][2]), "r"(af[mi][3]),
                          "r"(b0), "r"(b1));
                }
        }
        st++; if (st >= NSTAGE) st = 0;
    }

    // Epilogue
    #pragma unroll
    for (int mi = 0; mi < 4; mi++) {
        const int r = row0 + wm + mi * 16 + g;

        float inv0 = 1.f, inv1 = 1.f;
        if (MODE == 3) {
            inv0 = 1.0f / rowsum[r];
            inv1 = 1.0f / rowsum[r + 8];
        }
        float s0 = 0.f, s1 = 0.f;

        #pragma unroll
        for (int ni = 0; ni < 8; ni++) {
            const int c = col0 + wn + ni * 8 + tig * 2;
            float v0x = acc[mi][ni][0], v0y = acc[mi][ni][1];
            float v1x = acc[mi][ni][2], v1y = acc[mi][ni][3];

            if (MODE == 2) {
                v0x = exp2f(alpha * v0x); v0y = exp2f(alpha * v0y);
                v1x = exp2f(alpha * v1x); v1y = exp2f(alpha * v1y);
                s0 += v0x + v0y; s1 += v1x + v1y;
            } else if (MODE == 3) {
                v0x *= inv0; v0y *= inv0; v1x *= inv1; v1y *= inv1;
            } else {
                v0x *= alpha; v0y *= alpha; v1x *= alpha; v1y *= alpha;
            }
            if (MODE == 1) {
                *reinterpret_cast<float2*>(&Cf[(size_t)r * ldc + c]) = make_float2(v0x, v0y);
                *reinterpret_cast<float2*>(&Cf[(size_t)(r + 8) * ldc + c]) = make_float2(v1x, v1y);
            } else {
                *reinterpret_cast<__half2*>(&Ch[(size_t)r * ldc + c]) =
                    __floats2half2_rn(v0x, v0y);
                *reinterpret_cast<__half2*>(&Ch[(size_t)(r + 8) * ldc + c]) =
                    __floats2half2_rn(v1x, v1y);
            }
        }

        if (MODE == 2) {
            s0 += __shfl_xor_sync(0xffffffffu, s0, 1);
            s0 += __shfl_xor_sync(0xffffffffu, s0, 2);
            s1 += __shfl_xor_sync(0xffffffffu, s1, 1);
            s1 += __shfl_xor_sync(0xffffffffu, s1, 2);
            if (tig == 0) {
                atomicAdd(&rowsum[r], s0);
                atomicAdd(&rowsum[r + 8], s1);
            }
        }
    }
    #undef LOAD_TILE
}

// Elementwise float -> half
__global__ __launch_bounds__(256)
void f2h_kernel(const float* __restrict__ src, __half* __restrict__ dst, int n4)
{
    int i = blockIdx.x * 256 + threadIdx.x;
    if (i < n4) {
        float4 v = reinterpret_cast<const float4*>(src)[i];
        reinterpret_cast<__half2*>(dst)[2 * i]     = __floats2half2_rn(v.x, v.y);
        reinterpret_cast<__half2*>(dst)[2 * i + 1] = __floats2half2_rn(v.z, v.w);
    }
}

// Batched f2h over the four weight matrices (all 768*6144 = 4.7M elements)
__global__ __launch_bounds__(256)
void f2h_w4(const float* __restrict__ s0, const float* __restrict__ s1,
            const float* __restrict__ s2, const float* __restrict__ s3,
            __half* __restrict__ dst, int n4, long dstride)
{
    const int z = blockIdx.z;
    const float* src = (z == 0) ? s0 : (z == 1) ? s1 : (z == 2) ? s2 : s3;
    dst += (long)z * dstride;
    int i = blockIdx.x * 256 + threadIdx.x;
    if (i < n4) {
        float4 v = reinterpret_cast<const float4*>(src)[i];
        reinterpret_cast<__half2*>(dst)[2 * i]     = __floats2half2_rn(v.x, v.y);
        reinterpret_cast<__half2*>(dst)[2 * i + 1] = __floats2half2_rn(v.z, v.w);
    }
}

// Zero rowsum
__global__ __launch_bounds__(256)
void zero_kernel(float* __restrict__ p, int n)
{
    int i = blockIdx.x * 256 + threadIdx.x;
    if (i < n) p[i] = 0.f;
}

// Split-K reduce: out = sum_s psum[s] + bias
__global__ __launch_bounds__(256)
void reduce_kernel(const float* __restrict__ psum, const float* __restrict__ bias,
                   float* __restrict__ out, int n4)
{
    int i = blockIdx.x * 256 + threadIdx.x;
    if (i >= n4) return;
    const int col = (i * 4) % EE;
    float4 b4 = *reinterpret_cast<const float4*>(&bias[col]);
    float4 a = reinterpret_cast<const float4*>(psum)[i];
    float4 b = reinterpret_cast<const float4*>(psum + (size_t)MR * EE)[i];
    float4 c = reinterpret_cast<const float4*>(psum + (size_t)2 * MR * EE)[i];
    float4 o;
    o.x = a.x + b.x + c.x + b4.x;
    o.y = a.y + b.y + c.y + b4.y;
    o.z = a.z + b.z + c.z + b4.z;
    o.w = a.w + b.w + c.w + b4.w;
    reinterpret_cast<float4*>(out)[i] = o;
}

// ---------------------------------------------------------------------------
extern "C" void kernel_launch(void* const* d_in, const int* in_sizes, int n_in,
                              void* d_out, int out_size)
{
    const float* x  = (const float*)d_in[0];   // [4,2048,768]
    const float* Wq = (const float*)d_in[1];   // [768,6144]
    const float* Wk = (const float*)d_in[2];
    const float* Wv = (const float*)d_in[3];
    const float* Wu = (const float*)d_in[4];   // [6144,768]
    const float* bu = (const float*)d_in[5];   // [768]
    float* out = (float*)d_out;                // [8192,768]

    __half *x16, *w16, *qkv, *p16, *ho;
    float *rowsum, *psum;
    cudaGetSymbolAddress((void**)&x16,    g_x16);
    cudaGetSymbolAddress((void**)&w16,    g_w16);
    cudaGetSymbolAddress((void**)&qkv,    g_qkv);
    cudaGetSymbolAddress((void**)&p16,    g_p16);
    cudaGetSymbolAddress((void**)&rowsum, g_rowsum);
    cudaGetSymbolAddress((void**)&ho,     g_ho);
    cudaGetSymbolAddress((void**)&psum,   g_psum);

    __half* q = qkv;
    __half* k = qkv + (size_t)MR * HE;
    __half* v = qkv + (size_t)2 * MR * HE;
    const long WSZ = (long)HE * EE;
    __half* w16u = w16 + 3 * WSZ;              // Wu fp16, native [6144,768]

    cudaFuncSetAttribute(hgemm<0, true >, cudaFuncAttributeMaxDynamicSharedMemorySize, SMEM_TOTAL);
    cudaFuncSetAttribute(hgemm<1, true >, cudaFuncAttributeMaxDynamicSharedMemorySize, SMEM_TOTAL);
    cudaFuncSetAttribute(hgemm<2, false>, cudaFuncAttributeMaxDynamicSharedMemorySize, SMEM_TOTAL);
    cudaFuncSetAttribute(hgemm<3, true >, cudaFuncAttributeMaxDynamicSharedMemorySize, SMEM_TOTAL);

    const dim3 blk(256);
    const dim3 gblk(256);
    const float alpha_exp = 1.4426950408889634f / sqrtf((float)EE);
    const int WN4 = (int)(WSZ / 4);

    // 0: zero rowsum; 1: x -> fp16; 2: weights -> fp16 (native layout, z=4)
    zero_kernel<<<(BB * HH * TT + 255) / 256, blk>>>(rowsum, BB * HH * TT);
    f2h_kernel<<<(MR * EE / 4 + 255) / 256, blk>>>(x, x16, MR * EE / 4);
    f2h_w4<<<dim3((WN4 + 255) / 256, 1, 4), blk>>>(Wq, Wk, Wv, Wu, w16, WN4, WSZ);

    // 3: QKV projections (batched z=3), B = W (N-major, trans-load)
    hgemm<0, true><<<dim3(HE/128, MR/256, 3), gblk, SMEM_TOTAL>>>(
        x16, w16, qkv, nullptr,
        EE, EE, HE, HE,
        1, 0, 0, WSZ, 0, (long)MR * HE, 0, 1.f);

    // 4: scores + exp + rowsum (B = k, K-major)
    hgemm<2, false><<<dim3(TT/128, TT/256, BB*HH), gblk, SMEM_TOTAL>>>(
        q, k, p16, rowsum,
        EE, HE, HE, TT,
        HH, (long)TT * HE, (long)EE, (long)TT * HE, (long)EE,
        (long)HH * TT * TT, (long)TT * TT, alpha_exp);

    // 5: O = (p @ v) / rowsum -> ho fp16  (B = v, N-major trans-load)
    hgemm<3, true><<<dim3(EE/128, TT/256, BB*HH), gblk, SMEM_TOTAL>>>(
        p16, v, ho, rowsum,
        TT, TT, HE, HE,
        HH, (long)HH * TT * TT, (long)TT * TT,
        (long)TT * HE, (long)EE,
        (long)TT * HE, (long)EE, 1.f);

    // 6: output projection, split-K=3 (B = Wu, N-major trans-load)
    hgemm<1, true><<<dim3(EE/128, MR/256, NSPLIT), gblk, SMEM_TOTAL>>>(
        ho, w16u, psum, nullptr,
        HE / NSPLIT, HE, EE, EE,
        1, (long)(HE / NSPLIT), 0, (long)(HE / NSPLIT) * EE, 0,
        (long)MR * EE, 0, 1.f);

    // 7: reduce partials + bias -> fp32 out
    reduce_kernel<<<(MR * EE / 4 + 255) / 256, blk>>>(psum, bu, out, MR * EE / 4);
}

// round 15
// speedup vs baseline: 1.0988x; 1.0988x over previous
#include <cuda_runtime.h>
#include <cuda_fp16.h>
#include <math.h>
#include <stdint.h>

// Problem shape (fixed by the reference)
#define BB 4
#define TT 2048
#define EE 768
#define HH 8
#define HE 6144          // H*E
#define MR 8192          // B*T
#define NSPLIT 3         // split-K for final projection

// Scratch (allocation-free rule -> __device__ globals)
__device__ __half g_x16[(size_t)MR * EE];                 // x in fp16
__device__ __half g_w16[(size_t)4 * HE * EE];             // Wq|Wk|Wv|Wu fp16 (native layout)
__device__ __half g_qkv[(size_t)3 * MR * HE];             // q|k|v fp16
__device__ __half g_p16[(size_t)BB * HH * (size_t)TT * TT]; // unnormalized exp(logit)
__device__ float  g_rowsum[(size_t)BB * HH * TT];         // per-row sum of exp
__device__ __half g_ho[(size_t)MR * HE];                  // attention out fp16
__device__ float  g_psum[(size_t)NSPLIT * MR * EE];       // split-K partials

// Tiling: CTA 128x128, BK=64 halfs, 8 warps (2Mx4N, 64x32 warp tile),
// 3-stage cp.async ring, XOR swizzle, 2 CTAs/SM -> 16 warps resident.
#define BKH 64
#define STAGE_BYTES 16384               // one operand tile: 16 KB
#define NSTAGE 3
#define SMEM_TOTAL (2 * NSTAGE * STAGE_BYTES)   // 98304 B

__device__ __forceinline__ void cp_async16(uint32_t smem_dst, const void* gmem_src) {
    asm volatile("cp.async.cg.shared.global [%0], [%1], 16;" :: "r"(smem_dst), "l"(gmem_src));
}
__device__ __forceinline__ void cp_commit() { asm volatile("cp.async.commit_group;" ::: "memory"); }
template<int N>
__device__ __forceinline__ void cp_wait() { asm volatile("cp.async.wait_group %0;" :: "n"(N) : "memory"); }
__device__ __forceinline__ void ldsm_x4(uint32_t (&d)[4], uint32_t addr) {
    asm volatile("ldmatrix.sync.aligned.m8n8.x4.shared.b16 {%0,%1,%2,%3}, [%4];"
        : "=r"(d[0]), "=r"(d[1]), "=r"(d[2]), "=r"(d[3]) : "r"(addr));
}
__device__ __forceinline__ void ldsm_x4_t(uint32_t (&d)[4], uint32_t addr) {
    asm volatile("ldmatrix.sync.aligned.m8n8.x4.trans.shared.b16 {%0,%1,%2,%3}, [%4];"
        : "=r"(d[0]), "=r"(d[1]), "=r"(d[2]), "=r"(d[3]) : "r"(addr));
}

// ---------------------------------------------------------------------------
// fp16 tensor-core GEMM (m16n8k16). C = alpha * A[M,K] @ B (+epilogue).
// TRANSB=false: B is K-major [N,K] rows (scores: B=k).
// TRANSB=true:  B is N-major [K,N] rows (W, v) -> ldmatrix.trans.
// MODE: 0 = fp16 out (alpha), 1 = fp32 out (alpha), 2 = EXPSUM, 3 = NORM.
// CTA 128x128, 8 warps (2 along M x 4 along N), warp tile 64x32.
// 2 CTAs/SM -> 16 warps resident (latency/barrier hiding).
// ---------------------------------------------------------------------------
template<int MODE, bool TRANSB>
__global__ __launch_bounds__(256, 2)
void hgemm(const __half* __restrict__ A, const __half* __restrict__ B,
           void* __restrict__ Cv, float* __restrict__ rowsum,
           int K, int lda, int ldb, int ldc,
           int nh, long sAb, long sAh, long sBb, long sBh,
           long sCb, long sCh, float alpha)
{
    extern __shared__ __half smem[];
    const uint32_t smem_u = (uint32_t)__cvta_generic_to_shared(smem);

    const int bz = blockIdx.z;
    const int bb = bz / nh;
    const int hh = bz - bb * nh;
    A += (long)bb * sAb + (long)hh * sAh;
    B += (long)bb * sBb + (long)hh * sBh;
    float*  Cf = (float*)Cv  + bb * sCb + hh * sCh;
    __half* Ch = (__half*)Cv + bb * sCb + hh * sCh;
    if (MODE == 2 || MODE == 3) rowsum += (long)bz * TT;

    const int tid  = threadIdx.x;
    const int warp = tid >> 5, lane = tid & 31;
    const int g    = lane >> 2, tig = lane & 3;
    const int r8   = lane & 7, j = lane >> 3;      // LDSM lane roles
    const int wm   = (warp >> 2) * 64;   // 2 warps along M
    const int wn   = (warp & 3)  * 32;   // 4 warps along N
    const int row0 = blockIdx.y * 128;
    const int col0 = blockIdx.x * 128;

    // A fragments (K-major, 128B rows): rowbase + ((csel + kf*32) ^ xm)
    uint32_t arow[4], axm[4];
    const uint32_t acsel = (uint32_t)(j >> 1) << 4;
    #pragma unroll
    for (int mi = 0; mi < 4; mi++) {
        int r = wm + mi * 16 + (j & 1) * 8 + r8;
        arow[mi] = (uint32_t)r << 7;
        axm[mi]  = (uint32_t)(r & 7) << 4;
    }
    // B fragments (warp covers 32 N -> 2 blocks)
    uint32_t brow[2], bxm[2];            // non-trans (K-major 128B rows)
    uint32_t btb[2];                     // trans (N-major 256B rows)
    const uint32_t bcsel = (uint32_t)(j & 1) << 4;
    if (!TRANSB) {
        #pragma unroll
        for (int p = 0; p < 2; p++) {
            int r = wn + p * 16 + (j >> 1) * 8 + r8;
            brow[p] = (uint32_t)r << 7;
            bxm[p]  = (uint32_t)(r & 7) << 4;
        }
    } else {
        // block j: row = (j&1)*8 + r8 (k-oct), col = wn*2 + p*32 + (j>>1)*16
        // swizzle XOR applied to the FULL 16B-aligned column offset (< 256)
        const uint32_t xtm = (uint32_t)r8 << 4;
        #pragma unroll
        for (int p = 0; p < 2; p++)
            btb[p] = (uint32_t)((j & 1) * 8 + r8) * 256
                   + (((uint32_t)(wn * 2 + p * 32 + (j >> 1) * 16)) ^ xtm);
    }

    float acc[4][4][4] = {};  // [mi][ni][reg]

    // Loaders (256 threads). A: 128 rows x 128B -> 4 passes, rr = tid>>3 + p*32.
    // B non-trans: same. B trans: 64 rows x 256B -> 4 passes, rr = tid>>4 + p*16.
    const int a_rr = tid >> 3;
    const uint32_t a_cb = (uint32_t)(tid & 7) << 4;
    const int t_rr = tid >> 4;
    const uint32_t t_c16 = (uint32_t)(tid & 15) << 4;

    #define LOAD_TILE(KT, ST)                                                         \
    {                                                                                 \
        const int _k0 = (KT) * BKH;                                                   \
        const uint32_t _sa = smem_u + (ST) * STAGE_BYTES;                             \
        const uint32_t _sb = smem_u + (NSTAGE + (ST)) * STAGE_BYTES;                  \
        _Pragma("unroll")                                                             \
        for (int p = 0; p < 4; p++) {                                                 \
            int rr = a_rr + p * 32;                                                   \
            uint32_t off = ((uint32_t)rr << 7) + (a_cb ^ ((uint32_t)(rr & 7) << 4));  \
            cp_async16(_sa + off, &A[(size_t)(row0 + rr) * lda + _k0 + (a_cb >> 1)]); \
        }                                                                             \
        if (TRANSB) {                                                                 \
            _Pragma("unroll")                                                         \
            for (int p = 0; p < 4; p++) {                                             \
                int rr = t_rr + p * 16;                                               \
                uint32_t off = ((uint32_t)rr << 8) + (t_c16 ^ ((uint32_t)(rr & 7) << 4)); \
                cp_async16(_sb + off, &B[(size_t)(_k0 + rr) * ldb + col0 + (t_c16 >> 1)]); \
            }                                                                         \
        } else {                                                                      \
            _Pragma("unroll")                                                         \
            for (int p = 0; p < 4; p++) {                                             \
                int rr = a_rr + p * 32;                                               \
                uint32_t off = ((uint32_t)rr << 7) + (a_cb ^ ((uint32_t)(rr & 7) << 4)); \
                cp_async16(_sb + off, &B[(size_t)(col0 + rr) * ldb + _k0 + (a_cb >> 1)]); \
            }                                                                         \
        }                                                                             \
        cp_commit();                                                                  \
    }

    const int nt = K / BKH;
    LOAD_TILE(0, 0);
    if (nt > 1) LOAD_TILE(1, 1);

    int st = 0;
    for (int kt = 0; kt < nt; kt++) {
        if (kt + 1 < nt) cp_wait<1>(); else cp_wait<0>();
        __syncthreads();

        if (kt + 2 < nt) {
            int st2 = st + 2; if (st2 >= NSTAGE) st2 -= NSTAGE;
            LOAD_TILE(kt + 2, st2);
        }

        const uint32_t as_u = smem_u + st * STAGE_BYTES;
        const uint32_t bs_u = smem_u + (NSTAGE + st) * STAGE_BYTES;

        #pragma unroll
        for (int kf = 0; kf < 4; kf++) {          // 4 x k16 steps
            uint32_t af[4][4];
            uint32_t bf[2][4];
            #pragma unroll
            for (int p = 0; p < 2; p++) {
                ldsm_x4(af[p], as_u + arow[p] + ((acsel + (kf << 5)) ^ axm[p]));
                if (TRANSB) {
                    // kf advances 16 k-rows = 16*256 B; (row&7) unchanged
                    ldsm_x4_t(bf[p], bs_u + btb[p] + ((uint32_t)kf << 12));
                } else {
                    ldsm_x4(bf[p], bs_u + brow[p] + ((bcsel + (kf << 5)) ^ bxm[p]));
                }
            }
            #pragma unroll
            for (int p = 2; p < 4; p++)
                ldsm_x4(af[p], as_u + arow[p] + ((acsel + (kf << 5)) ^ axm[p]));

            #pragma unroll
            for (int mi = 0; mi < 4; mi++)
                #pragma unroll
                for (int ni = 0; ni < 4; ni++) {
                    const uint32_t b0 = bf[ni >> 1][(ni & 1) * 2 + 0];
                    const uint32_t b1 = bf[ni >> 1][(ni & 1) * 2 + 1];
                    asm volatile(
                        "mma.sync.aligned.m16n8k16.row.col.f32.f16.f16.f32 "
                        "{%0,%1,%2,%3},{%4,%5,%6,%7},{%8,%9},{%0,%1,%2,%3};"
                        : "+f"(acc[mi][ni][0]), "+f"(acc[mi][ni][1]),
                          "+f"(acc[mi][ni][2]), "+f"(acc[mi][ni][3])
                        : "r"(af[mi][0]), "r"(af[mi][1]), "r"(af[mi][2]), "r"(af[mi][3]),
                          "r"(b0), "r"(b1));
                }
        }
        st++; if (st >= NSTAGE) st = 0;
    }

    // Epilogue
    #pragma unroll
    for (int mi = 0; mi < 4; mi++) {
        const int r = row0 + wm + mi * 16 + g;

        float inv0 = 1.f, inv1 = 1.f;
        if (MODE == 3) {
            inv0 = 1.0f / rowsum[r];
            inv1 = 1.0f / rowsum[r + 8];
        }
        float s0 = 0.f, s1 = 0.f;

        #pragma unroll
        for (int ni = 0; ni < 4; ni++) {
            const int c = col0 + wn + ni * 8 + tig * 2;
            float v0x = acc[mi][ni][0], v0y = acc[mi][ni][1];
            float v1x = acc[mi][ni][2], v1y = acc[mi][ni][3];

            if (MODE == 2) {
                v0x = exp2f(alpha * v0x); v0y = exp2f(alpha * v0y);
                v1x = exp2f(alpha * v1x); v1y = exp2f(alpha * v1y);
                s0 += v0x + v0y; s1 += v1x + v1y;
            } else if (MODE == 3) {
                v0x *= inv0; v0y *= inv0; v1x *= inv1; v1y *= inv1;
            } else {
                v0x *= alpha; v0y *= alpha; v1x *= alpha; v1y *= alpha;
            }
            if (MODE == 1) {
                *reinterpret_cast<float2*>(&Cf[(size_t)r * ldc + c]) = make_float2(v0x, v0y);
                *reinterpret_cast<float2*>(&Cf[(size_t)(r + 8) * ldc + c]) = make_float2(v1x, v1y);
            } else {
                *reinterpret_cast<__half2*>(&Ch[(size_t)r * ldc + c]) =
                    __floats2half2_rn(v0x, v0y);
                *reinterpret_cast<__half2*>(&Ch[(size_t)(r + 8) * ldc + c]) =
                    __floats2half2_rn(v1x, v1y);
            }
        }

        if (MODE == 2) {
            s0 += __shfl_xor_sync(0xffffffffu, s0, 1);
            s0 += __shfl_xor_sync(0xffffffffu, s0, 2);
            s1 += __shfl_xor_sync(0xffffffffu, s1, 1);
            s1 += __shfl_xor_sync(0xffffffffu, s1, 2);
            if (tig == 0) {
                atomicAdd(&rowsum[r], s0);
                atomicAdd(&rowsum[r + 8], s1);
            }
        }
    }
    #undef LOAD_TILE
}

// Elementwise float -> half
__global__ __launch_bounds__(256)
void f2h_kernel(const float* __restrict__ src, __half* __restrict__ dst, int n4)
{
    int i = blockIdx.x * 256 + threadIdx.x;
    if (i < n4) {
        float4 v = reinterpret_cast<const float4*>(src)[i];
        reinterpret_cast<__half2*>(dst)[2 * i]     = __floats2half2_rn(v.x, v.y);
        reinterpret_cast<__half2*>(dst)[2 * i + 1] = __floats2half2_rn(v.z, v.w);
    }
}

// Batched f2h over the four weight matrices (all 768*6144 = 4.7M elements)
__global__ __launch_bounds__(256)
void f2h_w4(const float* __restrict__ s0, const float* __restrict__ s1,
            const float* __restrict__ s2, const float* __restrict__ s3,
            __half* __restrict__ dst, int n4, long dstride)
{
    const int z = blockIdx.z;
    const float* src = (z == 0) ? s0 : (z == 1) ? s1 : (z == 2) ? s2 : s3;
    dst += (long)z * dstride;
    int i = blockIdx.x * 256 + threadIdx.x;
    if (i < n4) {
        float4 v = reinterpret_cast<const float4*>(src)[i];
        reinterpret_cast<__half2*>(dst)[2 * i]     = __floats2half2_rn(v.x, v.y);
        reinterpret_cast<__half2*>(dst)[2 * i + 1] = __floats2half2_rn(v.z, v.w);
    }
}

// Zero rowsum
__global__ __launch_bounds__(256)
void zero_kernel(float* __restrict__ p, int n)
{
    int i = blockIdx.x * 256 + threadIdx.x;
    if (i < n) p[i] = 0.f;
}

// Split-K reduce: out = sum_s psum[s] + bias
__global__ __launch_bounds__(256)
void reduce_kernel(const float* __restrict__ psum, const float* __restrict__ bias,
                   float* __restrict__ out, int n4)
{
    int i = blockIdx.x * 256 + threadIdx.x;
    if (i >= n4) return;
    const int col = (i * 4) % EE;
    float4 b4 = *reinterpret_cast<const float4*>(&bias[col]);
    float4 a = reinterpret_cast<const float4*>(psum)[i];
    float4 b = reinterpret_cast<const float4*>(psum + (size_t)MR * EE)[i];
    float4 c = reinterpret_cast<const float4*>(psum + (size_t)2 * MR * EE)[i];
    float4 o;
    o.x = a.x + b.x + c.x + b4.x;
    o.y = a.y + b.y + c.y + b4.y;
    o.z = a.z + b.z + c.z + b4.z;
    o.w = a.w + b.w + c.w + b4.w;
    reinterpret_cast<float4*>(out)[i] = o;
}

// ---------------------------------------------------------------------------
extern "C" void kernel_launch(void* const* d_in, const int* in_sizes, int n_in,
                              void* d_out, int out_size)
{
    const float* x  = (const float*)d_in[0];   // [4,2048,768]
    const float* Wq = (const float*)d_in[1];   // [768,6144]
    const float* Wk = (const float*)d_in[2];
    const float* Wv = (const float*)d_in[3];
    const float* Wu = (const float*)d_in[4];   // [6144,768]
    const float* bu = (const float*)d_in[5];   // [768]
    float* out = (float*)d_out;                // [8192,768]

    __half *x16, *w16, *qkv, *p16, *ho;
    float *rowsum, *psum;
    cudaGetSymbolAddress((void**)&x16,    g_x16);
    cudaGetSymbolAddress((void**)&w16,    g_w16);
    cudaGetSymbolAddress((void**)&qkv,    g_qkv);
    cudaGetSymbolAddress((void**)&p16,    g_p16);
    cudaGetSymbolAddress((void**)&rowsum, g_rowsum);
    cudaGetSymbolAddress((void**)&ho,     g_ho);
    cudaGetSymbolAddress((void**)&psum,   g_psum);

    __half* q = qkv;
    __half* k = qkv + (size_t)MR * HE;
    __half* v = qkv + (size_t)2 * MR * HE;
    const long WSZ = (long)HE * EE;
    __half* w16u = w16 + 3 * WSZ;              // Wu fp16, native [6144,768]

    cudaFuncSetAttribute(hgemm<0, true >, cudaFuncAttributeMaxDynamicSharedMemorySize, SMEM_TOTAL);
    cudaFuncSetAttribute(hgemm<1, true >, cudaFuncAttributeMaxDynamicSharedMemorySize, SMEM_TOTAL);
    cudaFuncSetAttribute(hgemm<2, false>, cudaFuncAttributeMaxDynamicSharedMemorySize, SMEM_TOTAL);
    cudaFuncSetAttribute(hgemm<3, true >, cudaFuncAttributeMaxDynamicSharedMemorySize, SMEM_TOTAL);

    const dim3 blk(256);
    const dim3 gblk(256);
    const float alpha_exp = 1.4426950408889634f / sqrtf((float)EE);
    const int WN4 = (int)(WSZ / 4);

    // 0: zero rowsum; 1: x -> fp16; 2: weights -> fp16 (native layout, z=4)
    zero_kernel<<<(BB * HH * TT + 255) / 256, blk>>>(rowsum, BB * HH * TT);
    f2h_kernel<<<(MR * EE / 4 + 255) / 256, blk>>>(x, x16, MR * EE / 4);
    f2h_w4<<<dim3((WN4 + 255) / 256, 1, 4), blk>>>(Wq, Wk, Wv, Wu, w16, WN4, WSZ);

    // 3: QKV projections (batched z=3), B = W (N-major, trans-load)
    hgemm<0, true><<<dim3(HE/128, MR/128, 3), gblk, SMEM_TOTAL>>>(
        x16, w16, qkv, nullptr,
        EE, EE, HE, HE,
        1, 0, 0, WSZ, 0, (long)MR * HE, 0, 1.f);

    // 4: scores + exp + rowsum (B = k, K-major)
    hgemm<2, false><<<dim3(TT/128, TT/128, BB*HH), gblk, SMEM_TOTAL>>>(
        q, k, p16, rowsum,
        EE, HE, HE, TT,
        HH, (long)TT * HE, (long)EE, (long)TT * HE, (long)EE,
        (long)HH * TT * TT, (long)TT * TT, alpha_exp);

    // 5: O = (p @ v) / rowsum -> ho fp16  (B = v, N-major trans-load)
    hgemm<3, true><<<dim3(EE/128, TT/128, BB*HH), gblk, SMEM_TOTAL>>>(
        p16, v, ho, rowsum,
        TT, TT, HE, HE,
        HH, (long)HH * TT * TT, (long)TT * TT,
        (long)TT * HE, (long)EE,
        (long)TT * HE, (long)EE, 1.f);

    // 6: output projection, split-K=3 (B = Wu, N-major trans-load)
    hgemm<1, true><<<dim3(EE/128, MR/128, NSPLIT), gblk, SMEM_TOTAL>>>(
        ho, w16u, psum, nullptr,
        HE / NSPLIT, HE, EE, EE,
        1, (long)(HE / NSPLIT), 0, (long)(HE / NSPLIT) * EE, 0,
        (long)MR * EE, 0, 1.f);

    // 7: reduce partials + bias -> fp32 out
    reduce_kernel<<<(MR * EE / 4 + 255) / 256, blk>>>(psum, bu, out, MR * EE / 4);
}

// round 16
// speedup vs baseline: 1.1311x; 1.0294x over previous
#include <cuda_runtime.h>
#include <cuda_fp16.h>
#include <math.h>
#include <stdint.h>

// Problem shape (fixed by the reference)
#define BB 4
#define TT 2048
#define EE 768
#define HH 8
#define HE 6144          // H*E
#define MR 8192          // B*T
#define NSPLIT 3         // split-K for final projection

// Scratch (allocation-free rule -> __device__ globals)
__device__ __half g_x16[(size_t)MR * EE];                 // x in fp16
__device__ __half g_w16[(size_t)4 * HE * EE];             // Wq|Wk|Wv|Wu fp16 (native layout)
__device__ __half g_qkv[(size_t)3 * MR * HE];             // q|k|v fp16
__device__ __half g_p16[(size_t)BB * HH * (size_t)TT * TT]; // unnormalized exp(logit)
__device__ float  g_rowsum[(size_t)BB * HH * TT];         // per-row sum of exp
__device__ __half g_ho[(size_t)MR * HE];                  // attention out fp16
__device__ float  g_psum[(size_t)NSPLIT * MR * EE];       // split-K partials

// Tiling: CTA 128x128, BK=64 halfs, 4 warps (2Mx2N, 64x64 warp tile),
// 3-stage cp.async ring, XOR swizzle, 2 CTAs/SM.
#define BKH 64
#define STAGE_BYTES 16384               // one operand tile: 16 KB
#define NSTAGE 3
#define SMEM_TOTAL (2 * NSTAGE * STAGE_BYTES)   // 98304 B

__device__ __forceinline__ void cp_async16(uint32_t smem_dst, const void* gmem_src) {
    asm volatile("cp.async.cg.shared.global [%0], [%1], 16;" :: "r"(smem_dst), "l"(gmem_src));
}
__device__ __forceinline__ void cp_commit() { asm volatile("cp.async.commit_group;" ::: "memory"); }
template<int N>
__device__ __forceinline__ void cp_wait() { asm volatile("cp.async.wait_group %0;" :: "n"(N) : "memory"); }
__device__ __forceinline__ void ldsm_x4(uint32_t (&d)[4], uint32_t addr) {
    asm volatile("ldmatrix.sync.aligned.m8n8.x4.shared.b16 {%0,%1,%2,%3}, [%4];"
        : "=r"(d[0]), "=r"(d[1]), "=r"(d[2]), "=r"(d[3]) : "r"(addr));
}
__device__ __forceinline__ void ldsm_x4_t(uint32_t (&d)[4], uint32_t addr) {
    asm volatile("ldmatrix.sync.aligned.m8n8.x4.trans.shared.b16 {%0,%1,%2,%3}, [%4];"
        : "=r"(d[0]), "=r"(d[1]), "=r"(d[2]), "=r"(d[3]) : "r"(addr));
}

// ---------------------------------------------------------------------------
// fp16 tensor-core GEMM (m16n8k16). C = alpha * A[M,K] @ B (+epilogue).
// TRANSB=false: B is K-major [N,K] rows (scores: B=k).
// TRANSB=true:  B is N-major [K,N] rows (W, v) -> ldmatrix.trans.
// MODE: 0 = fp16 out (alpha), 1 = fp32 out (alpha), 2 = EXPSUM, 3 = NORM.
// 4 warps, warp tile 64x64, 3-stage cp.async ring.
// A-fragments double-buffered across kf steps (LDSM latency hiding).
// ---------------------------------------------------------------------------
template<int MODE, bool TRANSB>
__global__ __launch_bounds__(128, 2)
void hgemm(const __half* __restrict__ A, const __half* __restrict__ B,
           void* __restrict__ Cv, float* __restrict__ rowsum,
           int K, int lda, int ldb, int ldc,
           int nh, long sAb, long sAh, long sBb, long sBh,
           long sCb, long sCh, float alpha)
{
    extern __shared__ __half smem[];
    const uint32_t smem_u = (uint32_t)__cvta_generic_to_shared(smem);

    const int bz = blockIdx.z;
    const int bb = bz / nh;
    const int hh = bz - bb * nh;
    A += (long)bb * sAb + (long)hh * sAh;
    B += (long)bb * sBb + (long)hh * sBh;
    float*  Cf = (float*)Cv  + bb * sCb + hh * sCh;
    __half* Ch = (__half*)Cv + bb * sCb + hh * sCh;
    if (MODE == 2 || MODE == 3) rowsum += (long)bz * TT;

    const int tid  = threadIdx.x;
    const int warp = tid >> 5, lane = tid & 31;
    const int g    = lane >> 2, tig = lane & 3;
    const int r8   = lane & 7, j = lane >> 3;      // LDSM lane roles
    const int wm   = (warp >> 1) * 64;
    const int wn   = (warp & 1)  * 64;
    const int row0 = blockIdx.y * 128;
    const int col0 = blockIdx.x * 128;

    // A fragments (K-major, 128B rows): rowbase + ((csel + kf*32) ^ xm)
    uint32_t arow[4], axm[4];
    const uint32_t acsel = (uint32_t)(j >> 1) << 4;
    #pragma unroll
    for (int mi = 0; mi < 4; mi++) {
        int r = wm + mi * 16 + (j & 1) * 8 + r8;
        arow[mi] = (uint32_t)r << 7;
        axm[mi]  = (uint32_t)(r & 7) << 4;
    }
    // B fragments
    uint32_t brow[4], bxm[4];            // non-trans (K-major 128B rows)
    uint32_t btb[4];                     // trans (N-major 256B rows)
    const uint32_t bcsel = (uint32_t)(j & 1) << 4;
    if (!TRANSB) {
        #pragma unroll
        for (int p = 0; p < 4; p++) {
            int r = wn + p * 16 + (j >> 1) * 8 + r8;
            brow[p] = (uint32_t)r << 7;
            bxm[p]  = (uint32_t)(r & 7) << 4;
        }
    } else {
        // block j: row = (j&1)*8 + r8 (k-oct), col = wn*2 + p*32 + (j>>1)*16
        // swizzle XOR applied to the FULL 16B-aligned column offset (< 256)
        const uint32_t xtm = (uint32_t)r8 << 4;
        #pragma unroll
        for (int p = 0; p < 4; p++)
            btb[p] = (uint32_t)((j & 1) * 8 + r8) * 256
                   + (((uint32_t)(wn * 2 + p * 32 + (j >> 1) * 16)) ^ xtm);
    }

    float acc[4][8][4] = {};  // [mi][ni][reg]

    // Loaders. A: 128 rows x 128B. B non-trans: same. B trans: 64 rows x 256B.
    const int a_rr = tid >> 3;                       // +p*16
    const uint32_t a_cb = (uint32_t)(tid & 7) << 4;
    const int t_rr = tid >> 4;                       // +p*8 (trans tile)
    const uint32_t t_c16 = (uint32_t)(tid & 15) << 4;

    #define LOAD_TILE(KT, ST)                                                         \
    {                                                                                 \
        const int _k0 = (KT) * BKH;                                                   \
        const uint32_t _sa = smem_u + (ST) * STAGE_BYTES;                             \
        const uint32_t _sb = smem_u + (NSTAGE + (ST)) * STAGE_BYTES;                  \
        _Pragma("unroll")                                                             \
        for (int p = 0; p < 8; p++) {                                                 \
            int rr = a_rr + p * 16;                                                   \
            uint32_t off = ((uint32_t)rr << 7) + (a_cb ^ ((uint32_t)(rr & 7) << 4));  \
            cp_async16(_sa + off, &A[(size_t)(row0 + rr) * lda + _k0 + (a_cb >> 1)]); \
        }                                                                             \
        if (TRANSB) {                                                                 \
            _Pragma("unroll")                                                         \
            for (int p = 0; p < 8; p++) {                                             \
                int rr = t_rr + p * 8;                                                \
                uint32_t off = ((uint32_t)rr << 8) + (t_c16 ^ ((uint32_t)(rr & 7) << 4)); \
                cp_async16(_sb + off, &B[(size_t)(_k0 + rr) * ldb + col0 + (t_c16 >> 1)]); \
            }                                                                         \
        } else {                                                                      \
            _Pragma("unroll")                                                         \
            for (int p = 0; p < 8; p++) {                                             \
                int rr = a_rr + p * 16;                                               \
                uint32_t off = ((uint32_t)rr << 7) + (a_cb ^ ((uint32_t)(rr & 7) << 4)); \
                cp_async16(_sb + off, &B[(size_t)(col0 + rr) * ldb + _k0 + (a_cb >> 1)]); \
            }                                                                         \
        }                                                                             \
        cp_commit();                                                                  \
    }

    #define LDSM_A(DST, KF)                                                           \
        _Pragma("unroll")                                                             \
        for (int p = 0; p < 4; p++)                                                   \
            ldsm_x4((DST)[p], as_u + arow[p] + ((acsel + ((KF) << 5)) ^ axm[p]));
    #define LDSM_B(DST, KF)                                                           \
        _Pragma("unroll")                                                             \
        for (int p = 0; p < 4; p++) {                                                 \
            if (TRANSB) ldsm_x4_t((DST)[p], bs_u + btb[p] + ((uint32_t)(KF) << 12));  \
            else ldsm_x4((DST)[p], bs_u + brow[p] + ((bcsel + ((KF) << 5)) ^ bxm[p]));\
        }

    const int nt = K / BKH;
    LOAD_TILE(0, 0);
    if (nt > 1) LOAD_TILE(1, 1);

    int st = 0;
    for (int kt = 0; kt < nt; kt++) {
        if (kt + 1 < nt) cp_wait<1>(); else cp_wait<0>();
        __syncthreads();

        if (kt + 2 < nt) {
            int st2 = st + 2; if (st2 >= NSTAGE) st2 -= NSTAGE;
            LOAD_TILE(kt + 2, st2);
        }

        const uint32_t as_u = smem_u + st * STAGE_BYTES;
        const uint32_t bs_u = smem_u + (NSTAGE + st) * STAGE_BYTES;

        uint32_t af[2][4][4];     // double-buffered A fragments
        uint32_t bf[4][4];
        LDSM_A(af[0], 0);         // prime kf=0 A fragments

        #pragma unroll
        for (int kf = 0; kf < 4; kf++) {          // 4 x k16 steps
            const int cur = kf & 1;
            LDSM_B(bf, kf);                        // B for this step
            if (kf < 3) LDSM_A(af[cur ^ 1], kf + 1);  // prefetch next A

            #pragma unroll
            for (int mi = 0; mi < 4; mi++)
                #pragma unroll
                for (int ni = 0; ni < 8; ni++) {
                    const uint32_t b0 = bf[ni >> 1][(ni & 1) * 2 + 0];
                    const uint32_t b1 = bf[ni >> 1][(ni & 1) * 2 + 1];
                    asm volatile(
                        "mma.sync.aligned.m16n8k16.row.col.f32.f16.f16.f32 "
                        "{%0,%1,%2,%3},{%4,%5,%6,%7},{%8,%9},{%0,%1,%2,%3};"
                        : "+f"(acc[mi][ni][0]), "+f"(acc[mi][ni][1]),
                          "+f"(acc[mi][ni][2]), "+f"(acc[mi][ni][3])
                        : "r"(af[cur][mi][0]), "r"(af[cur][mi][1]),
                          "r"(af[cur][mi][2]), "r"(af[cur][mi][3]),
                          "r"(b0), "r"(b1));
                }
        }
        st++; if (st >= NSTAGE) st = 0;
    }

    // Epilogue
    #pragma unroll
    for (int mi = 0; mi < 4; mi++) {
        const int r = row0 + wm + mi * 16 + g;

        float inv0 = 1.f, inv1 = 1.f;
        if (MODE == 3) {
            inv0 = 1.0f / rowsum[r];
            inv1 = 1.0f / rowsum[r + 8];
        }
        float s0 = 0.f, s1 = 0.f;

        #pragma unroll
        for (int ni = 0; ni < 8; ni++) {
            const int c = col0 + wn + ni * 8 + tig * 2;
            float v0x = acc[mi][ni][0], v0y = acc[mi][ni][1];
            float v1x = acc[mi][ni][2], v1y = acc[mi][ni][3];

            if (MODE == 2) {
                v0x = exp2f(alpha * v0x); v0y = exp2f(alpha * v0y);
                v1x = exp2f(alpha * v1x); v1y = exp2f(alpha * v1y);
                s0 += v0x + v0y; s1 += v1x + v1y;
            } else if (MODE == 3) {
                v0x *= inv0; v0y *= inv0; v1x *= inv1; v1y *= inv1;
            } else {
                v0x *= alpha; v0y *= alpha; v1x *= alpha; v1y *= alpha;
            }
            if (MODE == 1) {
                *reinterpret_cast<float2*>(&Cf[(size_t)r * ldc + c]) = make_float2(v0x, v0y);
                *reinterpret_cast<float2*>(&Cf[(size_t)(r + 8) * ldc + c]) = make_float2(v1x, v1y);
            } else {
                *reinterpret_cast<__half2*>(&Ch[(size_t)r * ldc + c]) =
                    __floats2half2_rn(v0x, v0y);
                *reinterpret_cast<__half2*>(&Ch[(size_t)(r + 8) * ldc + c]) =
                    __floats2half2_rn(v1x, v1y);
            }
        }

        if (MODE == 2) {
            s0 += __shfl_xor_sync(0xffffffffu, s0, 1);
            s0 += __shfl_xor_sync(0xffffffffu, s0, 2);
            s1 += __shfl_xor_sync(0xffffffffu, s1, 1);
            s1 += __shfl_xor_sync(0xffffffffu, s1, 2);
            if (tig == 0) {
                atomicAdd(&rowsum[r], s0);
                atomicAdd(&rowsum[r + 8], s1);
            }
        }
    }
    #undef LOAD_TILE
    #undef LDSM_A
    #undef LDSM_B
}

// Elementwise float -> half; also zeros the rowsum array (fused, one launch).
__global__ __launch_bounds__(256)
void f2h_kernel(const float* __restrict__ src, __half* __restrict__ dst, int n4,
                float* __restrict__ zbuf, int nz4)
{
    int i = blockIdx.x * 256 + threadIdx.x;
    if (i < n4) {
        float4 v = reinterpret_cast<const float4*>(src)[i];
        reinterpret_cast<__half2*>(dst)[2 * i]     = __floats2half2_rn(v.x, v.y);
        reinterpret_cast<__half2*>(dst)[2 * i + 1] = __floats2half2_rn(v.z, v.w);
    }
    if (i < nz4)
        reinterpret_cast<float4*>(zbuf)[i] = make_float4(0.f, 0.f, 0.f, 0.f);
}

// Batched f2h over the four weight matrices (all 768*6144 = 4.7M elements)
__global__ __launch_bounds__(256)
void f2h_w4(const float* __restrict__ s0, const float* __restrict__ s1,
            const float* __restrict__ s2, const float* __restrict__ s3,
            __half* __restrict__ dst, int n4, long dstride)
{
    const int z = blockIdx.z;
    const float* src = (z == 0) ? s0 : (z == 1) ? s1 : (z == 2) ? s2 : s3;
    dst += (long)z * dstride;
    int i = blockIdx.x * 256 + threadIdx.x;
    if (i < n4) {
        float4 v = reinterpret_cast<const float4*>(src)[i];
        reinterpret_cast<__half2*>(dst)[2 * i]     = __floats2half2_rn(v.x, v.y);
        reinterpret_cast<__half2*>(dst)[2 * i + 1] = __floats2half2_rn(v.z, v.w);
    }
}

// Split-K reduce: out = sum_s psum[s] + bias
__global__ __launch_bounds__(256)
void reduce_kernel(const float* __restrict__ psum, const float* __restrict__ bias,
                   float* __restrict__ out, int n4)
{
    int i = blockIdx.x * 256 + threadIdx.x;
    if (i >= n4) return;
    const int col = (i * 4) % EE;
    float4 b4 = *reinterpret_cast<const float4*>(&bias[col]);
    float4 a = reinterpret_cast<const float4*>(psum)[i];
    float4 b = reinterpret_cast<const float4*>(psum + (size_t)MR * EE)[i];
    float4 c = reinterpret_cast<const float4*>(psum + (size_t)2 * MR * EE)[i];
    float4 o;
    o.x = a.x + b.x + c.x + b4.x;
    o.y = a.y + b.y + c.y + b4.y;
    o.z = a.z + b.z + c.z + b4.z;
    o.w = a.w + b.w + c.w + b4.w;
    reinterpret_cast<float4*>(out)[i] = o;
}

// ---------------------------------------------------------------------------
extern "C" void kernel_launch(void* const* d_in, const int* in_sizes, int n_in,
                              void* d_out, int out_size)
{
    const float* x  = (const float*)d_in[0];   // [4,2048,768]
    const float* Wq = (const float*)d_in[1];   // [768,6144]
    const float* Wk = (const float*)d_in[2];
    const float* Wv = (const float*)d_in[3];
    const float* Wu = (const float*)d_in[4];   // [6144,768]
    const float* bu = (const float*)d_in[5];   // [768]
    float* out = (float*)d_out;                // [8192,768]

    __half *x16, *w16, *qkv, *p16, *ho;
    float *rowsum, *psum;
    cudaGetSymbolAddress((void**)&x16,    g_x16);
    cudaGetSymbolAddress((void**)&w16,    g_w16);
    cudaGetSymbolAddress((void**)&qkv,    g_qkv);
    cudaGetSymbolAddress((void**)&p16,    g_p16);
    cudaGetSymbolAddress((void**)&rowsum, g_rowsum);
    cudaGetSymbolAddress((void**)&ho,     g_ho);
    cudaGetSymbolAddress((void**)&psum,   g_psum);

    __half* q = qkv;
    __half* k = qkv + (size_t)MR * HE;
    __half* v = qkv + (size_t)2 * MR * HE;
    const long WSZ = (long)HE * EE;
    __half* w16u = w16 + 3 * WSZ;              // Wu fp16, native [6144,768]

    cudaFuncSetAttribute(hgemm<0, true >, cudaFuncAttributeMaxDynamicSharedMemorySize, SMEM_TOTAL);
    cudaFuncSetAttribute(hgemm<1, true >, cudaFuncAttributeMaxDynamicSharedMemorySize, SMEM_TOTAL);
    cudaFuncSetAttribute(hgemm<2, false>, cudaFuncAttributeMaxDynamicSharedMemorySize, SMEM_TOTAL);
    cudaFuncSetAttribute(hgemm<3, true >, cudaFuncAttributeMaxDynamicSharedMemorySize, SMEM_TOTAL);

    const dim3 blk(256);
    const dim3 gblk(128);
    const float alpha_exp = 1.4426950408889634f / sqrtf((float)EE);
    const int WN4 = (int)(WSZ / 4);

    // 0: x -> fp16 (+ zero rowsum, fused); 1: weights -> fp16 (z=4)
    f2h_kernel<<<(MR * EE / 4 + 255) / 256, blk>>>(x, x16, MR * EE / 4,
                                                   rowsum, BB * HH * TT / 4);
    f2h_w4<<<dim3((WN4 + 255) / 256, 1, 4), blk>>>(Wq, Wk, Wv, Wu, w16, WN4, WSZ);

    // 2: QKV projections (batched z=3), B = W (N-major, trans-load)
    hgemm<0, true><<<dim3(HE/128, MR/128, 3), gblk, SMEM_TOTAL>>>(
        x16, w16, qkv, nullptr,
        EE, EE, HE, HE,
        1, 0, 0, WSZ, 0, (long)MR * HE, 0, 1.f);

    // 3: scores + exp + rowsum (B = k, K-major)
    hgemm<2, false><<<dim3(TT/128, TT/128, BB*HH), gblk, SMEM_TOTAL>>>(
        q, k, p16, rowsum,
        EE, HE, HE, TT,
        HH, (long)TT * HE, (long)EE, (long)TT * HE, (long)EE,
        (long)HH * TT * TT, (long)TT * TT, alpha_exp);

    // 4: O = (p @ v) / rowsum -> ho fp16  (B = v, N-major trans-load)
    hgemm<3, true><<<dim3(EE/128, TT/128, BB*HH), gblk, SMEM_TOTAL>>>(
        p16, v, ho, rowsum,
        TT, TT, HE, HE,
        HH, (long)HH * TT * TT, (long)TT * TT,
        (long)TT * HE, (long)EE,
        (long)TT * HE, (long)EE, 1.f);

    // 5: output projection, split-K=3 (B = Wu, N-major trans-load)
    hgemm<1, true><<<dim3(EE/128, MR/128, NSPLIT), gblk, SMEM_TOTAL>>>(
        ho, w16u, psum, nullptr,
        HE / NSPLIT, HE, EE, EE,
        1, (long)(HE / NSPLIT), 0, (long)(HE / NSPLIT) * EE, 0,
        (long)MR * EE, 0, 1.f);

    // 6: reduce partials + bias -> fp32 out
    reduce_kernel<<<(MR * EE / 4 + 255) / 256, blk>>>(psum, bu, out, MR * EE / 4);
}